// round 4
// baseline (speedup 1.0000x reference)
#include <cuda_runtime.h>

__global__ void init_out_kernel(float* out) {
    out[0] = 0.0f;
}

__device__ __forceinline__ float4 ldcs4(const float4* p) {
    return __ldcs(p);
}

// Grid-stride SSE reduction, unroll x4 with front-batched loads for MLP.
__global__ void sse_reduce_kernel(const float4* __restrict__ p,
                                  const float4* __restrict__ t,
                                  float* __restrict__ out,
                                  int n4, float scale) {
    const int idx    = blockIdx.x * blockDim.x + threadIdx.x;
    const int stride = gridDim.x * blockDim.x;

    float acc0 = 0.0f, acc1 = 0.0f, acc2 = 0.0f, acc3 = 0.0f;

    // Main unrolled loop: 8 independent 16B loads issued before any math.
    int i = idx;
    for (; i + 3 * stride < n4; i += 4 * stride) {
        float4 a0 = ldcs4(&p[i]);
        float4 a1 = ldcs4(&p[i +     stride]);
        float4 a2 = ldcs4(&p[i + 2 * stride]);
        float4 a3 = ldcs4(&p[i + 3 * stride]);
        float4 b0 = ldcs4(&t[i]);
        float4 b1 = ldcs4(&t[i +     stride]);
        float4 b2 = ldcs4(&t[i + 2 * stride]);
        float4 b3 = ldcs4(&t[i + 3 * stride]);

        float d;
        d = a0.x - b0.x; acc0 = fmaf(d, d, acc0);
        d = a0.y - b0.y; acc0 = fmaf(d, d, acc0);
        d = a0.z - b0.z; acc0 = fmaf(d, d, acc0);
        d = a0.w - b0.w; acc0 = fmaf(d, d, acc0);
        d = a1.x - b1.x; acc1 = fmaf(d, d, acc1);
        d = a1.y - b1.y; acc1 = fmaf(d, d, acc1);
        d = a1.z - b1.z; acc1 = fmaf(d, d, acc1);
        d = a1.w - b1.w; acc1 = fmaf(d, d, acc1);
        d = a2.x - b2.x; acc2 = fmaf(d, d, acc2);
        d = a2.y - b2.y; acc2 = fmaf(d, d, acc2);
        d = a2.z - b2.z; acc2 = fmaf(d, d, acc2);
        d = a2.w - b2.w; acc2 = fmaf(d, d, acc2);
        d = a3.x - b3.x; acc3 = fmaf(d, d, acc3);
        d = a3.y - b3.y; acc3 = fmaf(d, d, acc3);
        d = a3.z - b3.z; acc3 = fmaf(d, d, acc3);
        d = a3.w - b3.w; acc3 = fmaf(d, d, acc3);
    }
    // Tail
    for (; i < n4; i += stride) {
        float4 a = ldcs4(&p[i]);
        float4 b = ldcs4(&t[i]);
        float d;
        d = a.x - b.x; acc0 = fmaf(d, d, acc0);
        d = a.y - b.y; acc0 = fmaf(d, d, acc0);
        d = a.z - b.z; acc0 = fmaf(d, d, acc0);
        d = a.w - b.w; acc0 = fmaf(d, d, acc0);
    }

    float acc = (acc0 + acc1) + (acc2 + acc3);

    // Warp reduction
    #pragma unroll
    for (int off = 16; off > 0; off >>= 1)
        acc += __shfl_down_sync(0xFFFFFFFFu, acc, off);

    __shared__ float warp_sums[8];
    const int lane = threadIdx.x & 31;
    const int wid  = threadIdx.x >> 5;
    if (lane == 0) warp_sums[wid] = acc;
    __syncthreads();

    if (wid == 0) {
        float v = (lane < (blockDim.x >> 5)) ? warp_sums[lane] : 0.0f;
        #pragma unroll
        for (int off = 4; off > 0; off >>= 1)
            v += __shfl_down_sync(0xFFFFFFFFu, v, off);
        if (lane == 0)
            atomicAdd(out, v * scale);
    }
}

extern "C" void kernel_launch(void* const* d_in, const int* in_sizes, int n_in,
                              void* d_out, int out_size) {
    const float* pred = (const float*)d_in[0];
    const float* targ = (const float*)d_in[1];
    float* out = (float*)d_out;

    int n = in_sizes[0];       // B * S * 2 = 16,769,024 (divisible by 4)
    int n4 = n / 4;
    float scale = 2.0f / (float)n;

    init_out_kernel<<<1, 1>>>(out);

    const int threads = 256;
    const int blocks = 592;    // 4 CTAs per SM on 148 SMs, single wave
    sse_reduce_kernel<<<blocks, threads>>>((const float4*)pred,
                                           (const float4*)targ,
                                           out, n4, scale);
}

// round 5
// speedup vs baseline: 1.0651x; 1.0651x over previous
#include <cuda_runtime.h>

#define NBLOCKS 1184
#define NTHREADS 256

__device__ float g_partials[NBLOCKS];
__device__ unsigned int g_done_count = 0;

__device__ __forceinline__ float4 ldcs4(const float4* p) {
    return __ldcs(p);
}

// Single-kernel SSE reduction: grid-stride unroll x4 with front-batched
// loads, block partials to a device global, last-block-done finish.
__global__ void __launch_bounds__(NTHREADS, 8)
sse_reduce_kernel(const float4* __restrict__ p,
                  const float4* __restrict__ t,
                  float* __restrict__ out,
                  int n4, float scale) {
    const int idx    = blockIdx.x * blockDim.x + threadIdx.x;
    const int stride = gridDim.x * blockDim.x;

    float acc0 = 0.0f, acc1 = 0.0f, acc2 = 0.0f, acc3 = 0.0f;

    int i = idx;
    for (; i + 3 * stride < n4; i += 4 * stride) {
        float4 a0 = ldcs4(&p[i]);
        float4 a1 = ldcs4(&p[i +     stride]);
        float4 a2 = ldcs4(&p[i + 2 * stride]);
        float4 a3 = ldcs4(&p[i + 3 * stride]);
        float4 b0 = ldcs4(&t[i]);
        float4 b1 = ldcs4(&t[i +     stride]);
        float4 b2 = ldcs4(&t[i + 2 * stride]);
        float4 b3 = ldcs4(&t[i + 3 * stride]);

        float d;
        d = a0.x - b0.x; acc0 = fmaf(d, d, acc0);
        d = a0.y - b0.y; acc0 = fmaf(d, d, acc0);
        d = a0.z - b0.z; acc0 = fmaf(d, d, acc0);
        d = a0.w - b0.w; acc0 = fmaf(d, d, acc0);
        d = a1.x - b1.x; acc1 = fmaf(d, d, acc1);
        d = a1.y - b1.y; acc1 = fmaf(d, d, acc1);
        d = a1.z - b1.z; acc1 = fmaf(d, d, acc1);
        d = a1.w - b1.w; acc1 = fmaf(d, d, acc1);
        d = a2.x - b2.x; acc2 = fmaf(d, d, acc2);
        d = a2.y - b2.y; acc2 = fmaf(d, d, acc2);
        d = a2.z - b2.z; acc2 = fmaf(d, d, acc2);
        d = a2.w - b2.w; acc2 = fmaf(d, d, acc2);
        d = a3.x - b3.x; acc3 = fmaf(d, d, acc3);
        d = a3.y - b3.y; acc3 = fmaf(d, d, acc3);
        d = a3.z - b3.z; acc3 = fmaf(d, d, acc3);
        d = a3.w - b3.w; acc3 = fmaf(d, d, acc3);
    }
    for (; i < n4; i += stride) {
        float4 a = ldcs4(&p[i]);
        float4 b = ldcs4(&t[i]);
        float d;
        d = a.x - b.x; acc0 = fmaf(d, d, acc0);
        d = a.y - b.y; acc0 = fmaf(d, d, acc0);
        d = a.z - b.z; acc0 = fmaf(d, d, acc0);
        d = a.w - b.w; acc0 = fmaf(d, d, acc0);
    }

    float acc = (acc0 + acc1) + (acc2 + acc3);

    // Warp reduction
    #pragma unroll
    for (int off = 16; off > 0; off >>= 1)
        acc += __shfl_down_sync(0xFFFFFFFFu, acc, off);

    __shared__ float warp_sums[NTHREADS / 32];
    const int lane = threadIdx.x & 31;
    const int wid  = threadIdx.x >> 5;
    if (lane == 0) warp_sums[wid] = acc;
    __syncthreads();

    __shared__ bool is_last;
    if (wid == 0) {
        float v = (lane < (NTHREADS / 32)) ? warp_sums[lane] : 0.0f;
        #pragma unroll
        for (int off = 4; off > 0; off >>= 1)
            v += __shfl_down_sync(0xFFFFFFFFu, v, off);
        if (lane == 0) {
            g_partials[blockIdx.x] = v;
            __threadfence();
            unsigned int prev = atomicAdd(&g_done_count, 1u);
            is_last = (prev == (unsigned int)(gridDim.x - 1));
        }
    }
    __syncthreads();

    // Last block to finish reduces all partials and writes the result.
    if (is_last) {
        float v = 0.0f;
        for (int b = threadIdx.x; b < (int)gridDim.x; b += NTHREADS)
            v += g_partials[b];
        #pragma unroll
        for (int off = 16; off > 0; off >>= 1)
            v += __shfl_down_sync(0xFFFFFFFFu, v, off);
        if (lane == 0) warp_sums[wid] = v;
        __syncthreads();
        if (wid == 0) {
            float s = (lane < (NTHREADS / 32)) ? warp_sums[lane] : 0.0f;
            #pragma unroll
            for (int off = 4; off > 0; off >>= 1)
                s += __shfl_down_sync(0xFFFFFFFFu, s, off);
            if (lane == 0) {
                out[0] = s * scale;
                g_done_count = 0;   // reset for next graph replay
            }
        }
    }
}

extern "C" void kernel_launch(void* const* d_in, const int* in_sizes, int n_in,
                              void* d_out, int out_size) {
    const float* pred = (const float*)d_in[0];
    const float* targ = (const float*)d_in[1];
    float* out = (float*)d_out;

    int n = in_sizes[0];       // B * S * 2 = 16,769,024 (divisible by 4)
    int n4 = n / 4;
    float scale = 2.0f / (float)n;

    sse_reduce_kernel<<<NBLOCKS, NTHREADS>>>((const float4*)pred,
                                             (const float4*)targ,
                                             out, n4, scale);
}